// round 1
// baseline (speedup 1.0000x reference)
#include <cuda_runtime.h>
#include <cstdint>

#define NN 100000
#define EE 1600000
#define DD 128

// ---------------- scratch (device globals: no allocation allowed) ----------------
__device__ int   g_counts[NN];                 // in-degree per node (int)
__device__ int   g_offsets[NN];                // CSR row start
__device__ int   g_fill[NN];                   // scatter cursor (copy of offsets)
__device__ float g_deginv[NN];                 // 1/max(deg,1)
__device__ int   g_csr_src[EE];                // src ids grouped by dst
__device__ float g_mean[(size_t)NN * DD];      // mean-aggregated neighbors
__device__ float g_h[(size_t)NN * DD];         // layer-1 activations

// ---------------- CSR build ----------------
__global__ void zero_counts_kernel() {
    int i = blockIdx.x * blockDim.x + threadIdx.x;
    if (i < NN) g_counts[i] = 0;
}

__global__ void hist_kernel(const int* __restrict__ dst) {
    int i = blockIdx.x * blockDim.x + threadIdx.x;
    if (i < EE) atomicAdd(&g_counts[dst[i]], 1);
}

// single-block exclusive scan over g_counts -> g_offsets/g_fill, plus 1/deg
__global__ void scan_kernel() {
    __shared__ int warp_sums[32];
    __shared__ int carry;
    int tid  = threadIdx.x;
    int lane = tid & 31;
    int warp = tid >> 5;
    if (tid == 0) carry = 0;
    __syncthreads();
    for (int base = 0; base < NN; base += 1024) {
        int i = base + tid;
        int v = (i < NN) ? g_counts[i] : 0;
        int x = v;
        #pragma unroll
        for (int o = 1; o < 32; o <<= 1) {
            int t = __shfl_up_sync(0xffffffffu, x, o);
            if (lane >= o) x += t;
        }
        if (lane == 31) warp_sums[warp] = x;
        __syncthreads();
        if (warp == 0) {
            int w = warp_sums[lane];
            #pragma unroll
            for (int o = 1; o < 32; o <<= 1) {
                int t = __shfl_up_sync(0xffffffffu, w, o);
                if (lane >= o) w += t;
            }
            warp_sums[lane] = w;
        }
        __syncthreads();
        int incl = x + (warp ? warp_sums[warp - 1] : 0) + carry;
        if (i < NN) {
            int excl = incl - v;
            g_offsets[i] = excl;
            g_fill[i]    = excl;
            g_deginv[i]  = 1.0f / (float)((v > 1) ? v : 1);
        }
        __syncthreads();
        if (tid == 1023) carry = incl;
        __syncthreads();
    }
}

__global__ void scatter_kernel(const int* __restrict__ src, const int* __restrict__ dst) {
    int i = blockIdx.x * blockDim.x + threadIdx.x;
    if (i < EE) {
        int d = dst[i];
        int p = atomicAdd(&g_fill[d], 1);
        g_csr_src[p] = src[i];
    }
}

// ---------------- mean aggregation: one warp per destination node ----------------
__global__ void agg_kernel(const float* __restrict__ x, float* __restrict__ outmean) {
    int gwarp = (blockIdx.x * blockDim.x + threadIdx.x) >> 5;
    int lane  = threadIdx.x & 31;
    if (gwarp >= NN) return;
    int s = g_offsets[gwarp];
    int e = s + g_counts[gwarp];
    float4 acc = make_float4(0.f, 0.f, 0.f, 0.f);
    for (int t = s; t < e; ++t) {
        int srcn = __ldg(&g_csr_src[t]);  // broadcast (same addr for all lanes)
        float4 v = *reinterpret_cast<const float4*>(x + (size_t)srcn * DD + lane * 4);
        acc.x += v.x; acc.y += v.y; acc.z += v.z; acc.w += v.w;
    }
    float di = g_deginv[gwarp];
    acc.x *= di; acc.y *= di; acc.z *= di; acc.w *= di;
    *reinterpret_cast<float4*>(outmean + (size_t)gwarp * DD + lane * 4) = acc;
}

// ---------------- fused GEMM: out = relu?([A1|A2] @ [Wself;Wneigh] + bias) --------
// M = NN, K = 256, N = 128. Block tile 128x128, K-chunk 32, 256 threads, 8x8/thread.
// Inner product uses packed fma.rn.f32x2 (2 MACs per fma-pipe issue).
#define TM 128
#define TN 128
#define TK 32

__global__ __launch_bounds__(256, 2) void gemm_fused_kernel(
    const float* __restrict__ A1,     // [NN,128] self features
    const float* __restrict__ A2,     // [NN,128] mean neighbor features
    const float* __restrict__ Wself,  // [128,128]
    const float* __restrict__ Wneigh, // [128,128]
    const float* __restrict__ bias,   // [128]
    float* __restrict__ out,          // [NN,128]
    int relu)
{
    __shared__ float As[TK][TM + 8];  // transposed A tile; +8 keeps rows 16B aligned
    __shared__ float Bs[TK][TN];

    int m0  = blockIdx.x * TM;
    int tid = threadIdx.x;
    int tx  = tid & 15;   // 0..15 -> output cols tx*8..tx*8+7
    int ty  = tid >> 4;   // 0..15 -> output rows ty*8..ty*8+7

    unsigned long long acc[8][4];
    #pragma unroll
    for (int i = 0; i < 8; ++i)
        #pragma unroll
        for (int j = 0; j < 4; ++j) acc[i][j] = 0ULL;

    for (int k0 = 0; k0 < 256; k0 += TK) {
        // --- load A tile (128 rows x 32 k) transposed into As ---
        #pragma unroll
        for (int t = 0; t < 4; ++t) {
            int f4i = tid + t * 256;          // 0..1023
            int row = f4i >> 3;               // 0..127
            int kq  = f4i & 7;                // 0..7 -> k = kq*4
            int gm  = m0 + row;
            int gk  = k0 + kq * 4;
            float4 v = make_float4(0.f, 0.f, 0.f, 0.f);
            if (gm < NN) {
                const float* srcp = (gk < DD)
                    ? (A1 + (size_t)gm * DD + gk)
                    : (A2 + (size_t)gm * DD + (gk - DD));
                v = *reinterpret_cast<const float4*>(srcp);
            }
            As[kq * 4 + 0][row] = v.x;
            As[kq * 4 + 1][row] = v.y;
            As[kq * 4 + 2][row] = v.z;
            As[kq * 4 + 3][row] = v.w;
        }
        // --- load B tile (32 k x 128 n) ---
        #pragma unroll
        for (int t = 0; t < 4; ++t) {
            int f4i  = tid + t * 256;         // 0..1023
            int krow = f4i >> 5;              // 0..31
            int nq   = f4i & 31;              // 0..31 -> n = nq*4
            int gk   = k0 + krow;
            const float* wsrc = (gk < DD)
                ? (Wself  + (size_t)gk * DD + nq * 4)
                : (Wneigh + (size_t)(gk - DD) * DD + nq * 4);
            *reinterpret_cast<float4*>(&Bs[krow][nq * 4]) =
                *reinterpret_cast<const float4*>(wsrc);
        }
        __syncthreads();

        #pragma unroll
        for (int kk = 0; kk < TK; ++kk) {
            float4 av0 = *reinterpret_cast<const float4*>(&As[kk][ty * 8]);
            float4 av1 = *reinterpret_cast<const float4*>(&As[kk][ty * 8 + 4]);
            ulonglong2 p0 = *reinterpret_cast<const ulonglong2*>(&Bs[kk][tx * 8]);
            ulonglong2 p1 = *reinterpret_cast<const ulonglong2*>(&Bs[kk][tx * 8 + 4]);
            unsigned long long b2[4] = {p0.x, p0.y, p1.x, p1.y};
            float av[8] = {av0.x, av0.y, av0.z, av0.w, av1.x, av1.y, av1.z, av1.w};
            #pragma unroll
            for (int i = 0; i < 8; ++i) {
                unsigned long long a2;
                asm("mov.b64 %0, {%1, %1};" : "=l"(a2) : "f"(av[i]));
                #pragma unroll
                for (int j = 0; j < 4; ++j) {
                    asm("fma.rn.f32x2 %0, %1, %2, %0;"
                        : "+l"(acc[i][j]) : "l"(a2), "l"(b2[j]));
                }
            }
        }
        __syncthreads();
    }

    // --- epilogue: bias (+relu) ---
    #pragma unroll
    for (int i = 0; i < 8; ++i) {
        int row = m0 + ty * 8 + i;
        if (row >= NN) continue;
        #pragma unroll
        for (int j = 0; j < 4; ++j) {
            float lo, hi;
            asm("mov.b64 {%0, %1}, %2;" : "=f"(lo), "=f"(hi) : "l"(acc[i][j]));
            int n = tx * 8 + j * 2;
            float2 bb = *reinterpret_cast<const float2*>(&bias[n]);
            lo += bb.x; hi += bb.y;
            if (relu) { lo = fmaxf(lo, 0.f); hi = fmaxf(hi, 0.f); }
            *reinterpret_cast<float2*>(&out[(size_t)row * DD + n]) = make_float2(lo, hi);
        }
    }
}

// ---------------- launch ----------------
extern "C" void kernel_launch(void* const* d_in, const int* in_sizes, int n_in,
                              void* d_out, int out_size) {
    const float* in_feat  = (const float*)d_in[0];
    const float* W1_self  = (const float*)d_in[1];
    const float* W1_neigh = (const float*)d_in[2];
    const float* b1       = (const float*)d_in[3];
    const float* W2_self  = (const float*)d_in[4];
    const float* W2_neigh = (const float*)d_in[5];
    const float* b2       = (const float*)d_in[6];
    const int*   src      = (const int*)d_in[7];
    const int*   dst      = (const int*)d_in[8];
    float* out = (float*)d_out;

    float* mean_p; cudaGetSymbolAddress((void**)&mean_p, g_mean);
    float* h_p;    cudaGetSymbolAddress((void**)&h_p, g_h);

    // CSR build (once; shared by both layers)
    zero_counts_kernel<<<(NN + 255) / 256, 256>>>();
    hist_kernel<<<(EE + 255) / 256, 256>>>(dst);
    scan_kernel<<<1, 1024>>>();
    scatter_kernel<<<(EE + 255) / 256, 256>>>(src, dst);

    int agg_grid  = (NN + 7) / 8;          // 8 warps per 256-thread block
    int gemm_grid = (NN + TM - 1) / TM;

    // layer 1
    agg_kernel<<<agg_grid, 256>>>(in_feat, mean_p);
    gemm_fused_kernel<<<gemm_grid, 256>>>(in_feat, mean_p, W1_self, W1_neigh, b1, h_p, 1);

    // layer 2
    agg_kernel<<<agg_grid, 256>>>(h_p, mean_p);
    gemm_fused_kernel<<<gemm_grid, 256>>>(h_p, mean_p, W2_self, W2_neigh, b2, out, 0);
}

// round 3
// speedup vs baseline: 1.6332x; 1.6332x over previous
#include <cuda_runtime.h>
#include <cuda_bf16.h>
#include <cstdint>

#define NN 100000
#define EE 1600000
#define DD 128
#define NB 98            // ceil(NN/1024)

// ---------------- scratch (device globals: no allocation allowed) ----------------
__device__ int   g_counts[NN];
__device__ int   g_offsets[NN];
__device__ int   g_fill[NN];
__device__ float g_deginv[NN];
__device__ int   g_bsums[128];
__device__ int   g_csr_src[EE];
__device__ float g_mean[(size_t)NN * DD];
__device__ float g_h[(size_t)NN * DD];

// ---------------- CSR build ----------------
__global__ void hist_kernel(const int* __restrict__ dst) {
    int i = blockIdx.x * blockDim.x + threadIdx.x;
    if (i < EE) atomicAdd(&g_counts[dst[i]], 1);
}

__global__ void scan_local_kernel() {
    __shared__ int wsums[32];
    int tid = threadIdx.x, lane = tid & 31, warp = tid >> 5;
    int i = blockIdx.x * 1024 + tid;
    int v = (i < NN) ? g_counts[i] : 0;
    int x = v;
    #pragma unroll
    for (int o = 1; o < 32; o <<= 1) {
        int t = __shfl_up_sync(0xffffffffu, x, o);
        if (lane >= o) x += t;
    }
    if (lane == 31) wsums[warp] = x;
    __syncthreads();
    if (warp == 0) {
        int w = wsums[lane];
        #pragma unroll
        for (int o = 1; o < 32; o <<= 1) {
            int t = __shfl_up_sync(0xffffffffu, w, o);
            if (lane >= o) w += t;
        }
        wsums[lane] = w;
    }
    __syncthreads();
    int incl = x + (warp ? wsums[warp - 1] : 0);
    if (i < NN) g_offsets[i] = incl - v;               // block-local exclusive
    if (tid == 1023) g_bsums[blockIdx.x] = incl;       // block total
}

__global__ void scan_bsums_kernel() {
    __shared__ int ws[4];
    int tid = threadIdx.x, lane = tid & 31, warp = tid >> 5;
    int v = (tid < NB) ? g_bsums[tid] : 0;
    int x = v;
    #pragma unroll
    for (int o = 1; o < 32; o <<= 1) {
        int t = __shfl_up_sync(0xffffffffu, x, o);
        if (lane >= o) x += t;
    }
    if (lane == 31) ws[warp] = x;
    __syncthreads();
    int add = 0;
    #pragma unroll
    for (int w = 0; w < 4; ++w) if (w < warp) add += ws[w];
    if (tid < NB) g_bsums[tid] = x - v + add;
}

__global__ void finalize_kernel() {
    int i = blockIdx.x * blockDim.x + threadIdx.x;
    if (i < NN) {
        int off = g_offsets[i] + g_bsums[i >> 10];
        g_offsets[i] = off;
        g_fill[i]    = off;
        int c = g_counts[i];
        g_deginv[i]  = 1.0f / (float)((c > 1) ? c : 1);
    }
}

__global__ void scatter_kernel(const int* __restrict__ src, const int* __restrict__ dst) {
    int i = blockIdx.x * blockDim.x + threadIdx.x;
    if (i < EE) {
        int d = dst[i];
        int p = atomicAdd(&g_fill[d], 1);
        g_csr_src[p] = src[i];
    }
}

// ---------------- mean aggregation: one warp per destination node ----------------
__global__ void agg_kernel(const float* __restrict__ x, float* __restrict__ outmean) {
    int gwarp = (blockIdx.x * blockDim.x + threadIdx.x) >> 5;
    int lane  = threadIdx.x & 31;
    if (gwarp >= NN) return;
    int s = g_offsets[gwarp];
    int e = s + g_counts[gwarp];
    float4 acc = make_float4(0.f, 0.f, 0.f, 0.f);
    for (int t = s; t < e; ++t) {
        int srcn = __ldg(&g_csr_src[t]);
        float4 v = *reinterpret_cast<const float4*>(x + (size_t)srcn * DD + lane * 4);
        acc.x += v.x; acc.y += v.y; acc.z += v.z; acc.w += v.w;
    }
    float di = g_deginv[gwarp];
    acc.x *= di; acc.y *= di; acc.z *= di; acc.w *= di;
    *reinterpret_cast<float4*>(outmean + (size_t)gwarp * DD + lane * 4) = acc;
}

// ================= tensor-core GEMM via mma.sync (bf16 hi/lo split) ===============
// out[M,128] = relu?([A1|A2][M,256] @ [Wself;Wneigh][256,128] + bias)
// Block: 128x128 tile, 256 threads = 8 warps (4x2), warp tile 32x64.
// K processed in chunks of 32; per chunk 3 products: Ah*Bh, Al*Bh, Ah*Bl.
// smem padded: A rows 40 bf16 (80B, 5 chunks), B rows 136 bf16 (272B, 17 chunks)
// -> ldmatrix conflict-free.

__device__ __forceinline__ uint32_t smem_u32(const void* p) {
    uint32_t a;
    asm("{ .reg .u64 t; cvta.to.shared.u64 t, %1; cvt.u32.u64 %0, t; }" : "=r"(a) : "l"(p));
    return a;
}
__device__ __forceinline__ void ldsm_x4(uint32_t& r0, uint32_t& r1, uint32_t& r2, uint32_t& r3, uint32_t a) {
    asm volatile("ldmatrix.sync.aligned.m8n8.x4.shared.b16 {%0,%1,%2,%3}, [%4];"
                 : "=r"(r0), "=r"(r1), "=r"(r2), "=r"(r3) : "r"(a));
}
__device__ __forceinline__ void ldsm_x4_t(uint32_t& r0, uint32_t& r1, uint32_t& r2, uint32_t& r3, uint32_t a) {
    asm volatile("ldmatrix.sync.aligned.m8n8.x4.trans.shared.b16 {%0,%1,%2,%3}, [%4];"
                 : "=r"(r0), "=r"(r1), "=r"(r2), "=r"(r3) : "r"(a));
}
__device__ __forceinline__ void mma_bf16(float* c, uint32_t a0, uint32_t a1, uint32_t a2, uint32_t a3,
                                         uint32_t b0, uint32_t b1) {
    asm volatile("mma.sync.aligned.m16n8k16.row.col.f32.bf16.bf16.f32 "
                 "{%0,%1,%2,%3}, {%4,%5,%6,%7}, {%8,%9}, {%0,%1,%2,%3};"
                 : "+f"(c[0]), "+f"(c[1]), "+f"(c[2]), "+f"(c[3])
                 : "r"(a0), "r"(a1), "r"(a2), "r"(a3), "r"(b0), "r"(b1));
}
__device__ __forceinline__ uint32_t pack_bf2(float x, float y) {
    __nv_bfloat162 t = __floats2bfloat162_rn(x, y);
    return *reinterpret_cast<uint32_t*>(&t);
}

#define APAD 40
#define BPAD 136

__global__ __launch_bounds__(256) void gemm_mma_kernel(
    const float* __restrict__ A1, const float* __restrict__ A2,
    const float* __restrict__ Wself, const float* __restrict__ Wneigh,
    const float* __restrict__ bias, float* __restrict__ out, int relu)
{
    __shared__ __nv_bfloat16 Ah[128][APAD];
    __shared__ __nv_bfloat16 Al[128][APAD];
    __shared__ __nv_bfloat16 Bh[32][BPAD];
    __shared__ __nv_bfloat16 Bl[32][BPAD];

    int tid = threadIdx.x, lane = tid & 31, wid = tid >> 5;
    int warp_m = wid & 3;            // 0..3 -> rows warp_m*32
    int warp_n = wid >> 2;           // 0..1 -> cols warp_n*64
    int m0 = blockIdx.x * 128;

    uint32_t ah_b = smem_u32(&Ah[0][0]);
    uint32_t al_b = smem_u32(&Al[0][0]);
    uint32_t bh_b = smem_u32(&Bh[0][0]);
    uint32_t bl_b = smem_u32(&Bl[0][0]);

    float acc[2][8][4];
    #pragma unroll
    for (int i = 0; i < 2; ++i)
        #pragma unroll
        for (int j = 0; j < 8; ++j)
            #pragma unroll
            for (int q = 0; q < 4; ++q) acc[i][j][q] = 0.f;

    // precomputed ldmatrix per-lane address components
    int a_lrow = lane & 15;                 // row within m16 tile
    int a_lcol = (lane >> 4) << 3;          // 0 or 8 (k offset)
    int b_lk   = lane & 15;                 // k within k16 tile
    int b_ln   = (lane >> 4) << 3;          // 0 or 8 (n offset)

    for (int ch = 0; ch < 8; ++ch) {
        int k0 = ch * 32;
        const float* Abase = (k0 < DD) ? A1 : A2;
        const float* Wbase = (k0 < DD) ? Wself : Wneigh;
        int cb = k0 & (DD - 1);   // 0,32,64,96

        __syncthreads();          // previous chunk fully consumed
        // --- A tile: 128 rows x 32 cols ---
        #pragma unroll
        for (int i = 0; i < 4; ++i) {
            int f = tid + i * 256;            // 0..1023
            int row = f >> 3, c4 = (f & 7) * 4;
            int gm = m0 + row;
            float4 v = make_float4(0.f, 0.f, 0.f, 0.f);
            if (gm < NN) v = *reinterpret_cast<const float4*>(Abase + (size_t)gm * DD + cb + c4);
            float hx = __bfloat162float(__float2bfloat16_rn(v.x));
            float hy = __bfloat162float(__float2bfloat16_rn(v.y));
            float hz = __bfloat162float(__float2bfloat16_rn(v.z));
            float hw = __bfloat162float(__float2bfloat16_rn(v.w));
            uint32_t* ph = reinterpret_cast<uint32_t*>(&Ah[row][c4]);
            ph[0] = pack_bf2(v.x, v.y); ph[1] = pack_bf2(v.z, v.w);
            uint32_t* pl = reinterpret_cast<uint32_t*>(&Al[row][c4]);
            pl[0] = pack_bf2(v.x - hx, v.y - hy); pl[1] = pack_bf2(v.z - hz, v.w - hw);
        }
        // --- B tile: 32 k-rows x 128 cols ---
        #pragma unroll
        for (int i = 0; i < 4; ++i) {
            int f = tid + i * 256;            // 0..1023
            int kr = f >> 5, n4 = (f & 31) * 4;
            float4 v = *reinterpret_cast<const float4*>(Wbase + (size_t)(cb + kr) * DD + n4);
            float hx = __bfloat162float(__float2bfloat16_rn(v.x));
            float hy = __bfloat162float(__float2bfloat16_rn(v.y));
            float hz = __bfloat162float(__float2bfloat16_rn(v.z));
            float hw = __bfloat162float(__float2bfloat16_rn(v.w));
            uint32_t* ph = reinterpret_cast<uint32_t*>(&Bh[kr][n4]);
            ph[0] = pack_bf2(v.x, v.y); ph[1] = pack_bf2(v.z, v.w);
            uint32_t* pl = reinterpret_cast<uint32_t*>(&Bl[kr][n4]);
            pl[0] = pack_bf2(v.x - hx, v.y - hy); pl[1] = pack_bf2(v.z - hz, v.w - hw);
        }
        __syncthreads();

        #pragma unroll
        for (int p = 0; p < 3; ++p) {
            uint32_t ab = (p == 1) ? al_b : ah_b;
            uint32_t bb = (p == 2) ? bl_b : bh_b;
            #pragma unroll
            for (int ks = 0; ks < 2; ++ks) {
                uint32_t a[2][4];
                #pragma unroll
                for (int mt = 0; mt < 2; ++mt) {
                    int row = warp_m * 32 + mt * 16 + a_lrow;
                    int col = ks * 16 + a_lcol;
                    ldsm_x4(a[mt][0], a[mt][1], a[mt][2], a[mt][3],
                            ab + (uint32_t)(row * APAD + col) * 2);
                }
                #pragma unroll
                for (int ng = 0; ng < 4; ++ng) {
                    int kk = ks * 16 + b_lk;
                    int nn = warp_n * 64 + ng * 16 + b_ln;
                    uint32_t b0, b1, b2, b3;
                    ldsm_x4_t(b0, b1, b2, b3, bb + (uint32_t)(kk * BPAD + nn) * 2);
                    #pragma unroll
                    for (int mt = 0; mt < 2; ++mt) {
                        mma_bf16(acc[mt][ng * 2 + 0], a[mt][0], a[mt][1], a[mt][2], a[mt][3], b0, b1);
                        mma_bf16(acc[mt][ng * 2 + 1], a[mt][0], a[mt][1], a[mt][2], a[mt][3], b2, b3);
                    }
                }
            }
        }
    }

    // --- epilogue ---
    int crow = lane >> 2;             // 0..7
    int ccol = (lane & 3) * 2;        // 0,2,4,6
    #pragma unroll
    for (int mt = 0; mt < 2; ++mt) {
        #pragma unroll
        for (int nt = 0; nt < 8; ++nt) {
            int col = warp_n * 64 + nt * 8 + ccol;
            float2 bb = __ldg(reinterpret_cast<const float2*>(bias + col));
            #pragma unroll
            for (int h = 0; h < 2; ++h) {      // d0/d1 (h=0) rows, d2/d3 (h=1) rows+8
                int row = m0 + warp_m * 32 + mt * 16 + crow + h * 8;
                if (row >= NN) continue;
                float lo = acc[mt][nt][h * 2 + 0] + bb.x;
                float hi = acc[mt][nt][h * 2 + 1] + bb.y;
                if (relu) { lo = fmaxf(lo, 0.f); hi = fmaxf(hi, 0.f); }
                *reinterpret_cast<float2*>(out + (size_t)row * DD + col) = make_float2(lo, hi);
            }
        }
    }
}

// ---------------- launch ----------------
extern "C" void kernel_launch(void* const* d_in, const int* in_sizes, int n_in,
                              void* d_out, int out_size) {
    const float* in_feat  = (const float*)d_in[0];
    const float* W1_self  = (const float*)d_in[1];
    const float* W1_neigh = (const float*)d_in[2];
    const float* b1       = (const float*)d_in[3];
    const float* W2_self  = (const float*)d_in[4];
    const float* W2_neigh = (const float*)d_in[5];
    const float* b2       = (const float*)d_in[6];
    const int*   src      = (const int*)d_in[7];
    const int*   dst      = (const int*)d_in[8];
    float* out = (float*)d_out;

    float* mean_p;   cudaGetSymbolAddress((void**)&mean_p, g_mean);
    float* h_p;      cudaGetSymbolAddress((void**)&h_p, g_h);
    int*   counts_p; cudaGetSymbolAddress((void**)&counts_p, g_counts);

    // CSR build
    cudaMemsetAsync(counts_p, 0, NN * sizeof(int));
    hist_kernel<<<(EE + 255) / 256, 256>>>(dst);
    scan_local_kernel<<<NB, 1024>>>();
    scan_bsums_kernel<<<1, 128>>>();
    finalize_kernel<<<(NN + 255) / 256, 256>>>();
    scatter_kernel<<<(EE + 255) / 256, 256>>>(src, dst);

    int agg_grid  = (NN + 7) / 8;
    int gemm_grid = (NN + 127) / 128;

    // layer 1
    agg_kernel<<<agg_grid, 256>>>(in_feat, mean_p);
    gemm_mma_kernel<<<gemm_grid, 256>>>(in_feat, mean_p, W1_self, W1_neigh, b1, h_p, 1);

    // layer 2
    agg_kernel<<<agg_grid, 256>>>(h_p, mean_p);
    gemm_mma_kernel<<<gemm_grid, 256>>>(h_p, mean_p, W2_self, W2_neigh, b2, out, 0);
}

// round 4
// speedup vs baseline: 1.6707x; 1.0229x over previous
#include <cuda_runtime.h>
#include <cuda_bf16.h>
#include <cstdint>

#define NN 100000
#define EE 1600000
#define DD 128
#define NB 98            // ceil(NN/1024)

// ---------------- scratch (device globals: no allocation allowed) ----------------
__device__ int   g_counts[NN];
__device__ int   g_offsets[NN];
__device__ int   g_fill[NN];
__device__ float g_deginv[NN];
__device__ int   g_bsums[128];
__device__ int   g_csr_src[EE];
// bf16 hi/lo feature buffers
__device__ __nv_bfloat16 g_xhi[(size_t)NN * DD];
__device__ __nv_bfloat16 g_xlo[(size_t)NN * DD];
__device__ __nv_bfloat16 g_mhi[(size_t)NN * DD];
__device__ __nv_bfloat16 g_mlo[(size_t)NN * DD];
__device__ __nv_bfloat16 g_hhi[(size_t)NN * DD];
__device__ __nv_bfloat16 g_hlo[(size_t)NN * DD];
// preconverted weights: [layer][256][128] (rows 0-127 = Wself, 128-255 = Wneigh)
__device__ __nv_bfloat16 g_whi[2 * 256 * DD];
__device__ __nv_bfloat16 g_wlo[2 * 256 * DD];

// ---------------- CSR build ----------------
__global__ void hist_kernel(const int* __restrict__ dst) {
    int i = blockIdx.x * blockDim.x + threadIdx.x;
    if (i < EE) atomicAdd(&g_counts[dst[i]], 1);
}

__global__ void scan_local_kernel() {
    __shared__ int wsums[32];
    int tid = threadIdx.x, lane = tid & 31, warp = tid >> 5;
    int i = blockIdx.x * 1024 + tid;
    int v = (i < NN) ? g_counts[i] : 0;
    int x = v;
    #pragma unroll
    for (int o = 1; o < 32; o <<= 1) {
        int t = __shfl_up_sync(0xffffffffu, x, o);
        if (lane >= o) x += t;
    }
    if (lane == 31) wsums[warp] = x;
    __syncthreads();
    if (warp == 0) {
        int w = wsums[lane];
        #pragma unroll
        for (int o = 1; o < 32; o <<= 1) {
            int t = __shfl_up_sync(0xffffffffu, w, o);
            if (lane >= o) w += t;
        }
        wsums[lane] = w;
    }
    __syncthreads();
    int incl = x + (warp ? wsums[warp - 1] : 0);
    if (i < NN) g_offsets[i] = incl - v;               // block-local exclusive
    if (tid == 1023) g_bsums[blockIdx.x] = incl;       // block total
}

// finalize with fused block-sums scan (each block redundantly scans 98 ints)
__global__ void finalize_kernel() {
    __shared__ int pref[NB];
    int tid = threadIdx.x;
    if (tid < NB) pref[tid] = g_bsums[tid];
    __syncthreads();
    if (tid == 0) {
        int run = 0;
        #pragma unroll 7
        for (int j = 0; j < NB; ++j) { int t = pref[j]; pref[j] = run; run += t; }
    }
    __syncthreads();
    int i = blockIdx.x * blockDim.x + tid;
    if (i < NN) {
        int off = g_offsets[i] + pref[i >> 10];
        g_offsets[i] = off;
        g_fill[i]    = off;
        int c = g_counts[i];
        g_deginv[i]  = 1.0f / (float)((c > 1) ? c : 1);
    }
}

__global__ void scatter_kernel(const int* __restrict__ src, const int* __restrict__ dst) {
    int i = blockIdx.x * blockDim.x + threadIdx.x;
    if (i < EE) {
        int d = dst[i];
        int p = atomicAdd(&g_fill[d], 1);
        g_csr_src[p] = src[i];
    }
}

// ---------------- converters ----------------
__global__ void convert_x_kernel(const float* __restrict__ x) {
    int i = blockIdx.x * blockDim.x + threadIdx.x;   // float4 index
    if (i >= NN * DD / 4) return;
    float4 v = *reinterpret_cast<const float4*>(x + (size_t)i * 4);
    float hx = __bfloat162float(__float2bfloat16_rn(v.x));
    float hy = __bfloat162float(__float2bfloat16_rn(v.y));
    float hz = __bfloat162float(__float2bfloat16_rn(v.z));
    float hw = __bfloat162float(__float2bfloat16_rn(v.w));
    __nv_bfloat162 h0 = __floats2bfloat162_rn(v.x, v.y);
    __nv_bfloat162 h1 = __floats2bfloat162_rn(v.z, v.w);
    __nv_bfloat162 l0 = __floats2bfloat162_rn(v.x - hx, v.y - hy);
    __nv_bfloat162 l1 = __floats2bfloat162_rn(v.z - hz, v.w - hw);
    uint2 hp = make_uint2(*(uint32_t*)&h0, *(uint32_t*)&h1);
    uint2 lp = make_uint2(*(uint32_t*)&l0, *(uint32_t*)&l1);
    reinterpret_cast<uint2*>(g_xhi)[i] = hp;
    reinterpret_cast<uint2*>(g_xlo)[i] = lp;
}

__global__ void convert_w_kernel(const float* __restrict__ W1s, const float* __restrict__ W1n,
                                 const float* __restrict__ W2s, const float* __restrict__ W2n) {
    int i = blockIdx.x * blockDim.x + threadIdx.x;   // float4 index, total 2*256*128/4 = 16384
    if (i >= 16384) return;
    int layer = i >> 13;               // 0/1
    int r256  = (i >> 5) & 255;        // row in [0,256)
    int c4    = i & 31;                // float4 within row
    const float* Wsrc = (layer == 0)
        ? ((r256 < 128) ? W1s + (size_t)r256 * DD : W1n + (size_t)(r256 - 128) * DD)
        : ((r256 < 128) ? W2s + (size_t)r256 * DD : W2n + (size_t)(r256 - 128) * DD);
    float4 v = *reinterpret_cast<const float4*>(Wsrc + c4 * 4);
    float hx = __bfloat162float(__float2bfloat16_rn(v.x));
    float hy = __bfloat162float(__float2bfloat16_rn(v.y));
    float hz = __bfloat162float(__float2bfloat16_rn(v.z));
    float hw = __bfloat162float(__float2bfloat16_rn(v.w));
    __nv_bfloat162 h0 = __floats2bfloat162_rn(v.x, v.y);
    __nv_bfloat162 h1 = __floats2bfloat162_rn(v.z, v.w);
    __nv_bfloat162 l0 = __floats2bfloat162_rn(v.x - hx, v.y - hy);
    __nv_bfloat162 l1 = __floats2bfloat162_rn(v.z - hz, v.w - hw);
    reinterpret_cast<uint2*>(g_whi)[i] = make_uint2(*(uint32_t*)&h0, *(uint32_t*)&h1);
    reinterpret_cast<uint2*>(g_wlo)[i] = make_uint2(*(uint32_t*)&l0, *(uint32_t*)&l1);
}

// ------------- mean aggregation (bf16 gather, fp32 accumulate, hi/lo out) --------
__global__ void agg_kernel(const __nv_bfloat16* __restrict__ x,
                           __nv_bfloat16* __restrict__ mh,
                           __nv_bfloat16* __restrict__ ml) {
    int gwarp = (blockIdx.x * blockDim.x + threadIdx.x) >> 5;
    int lane  = threadIdx.x & 31;
    if (gwarp >= NN) return;
    int s = g_offsets[gwarp];
    int e = s + g_counts[gwarp];
    const uint2* xr = reinterpret_cast<const uint2*>(x);
    float a0 = 0.f, a1 = 0.f, a2 = 0.f, a3 = 0.f;
    for (int t = s; t < e; ++t) {
        int srcn = __ldg(&g_csr_src[t]);
        uint2 v = __ldg(&xr[(size_t)srcn * 32 + lane]);
        float2 f0 = __bfloat1622float2(*reinterpret_cast<__nv_bfloat162*>(&v.x));
        float2 f1 = __bfloat1622float2(*reinterpret_cast<__nv_bfloat162*>(&v.y));
        a0 += f0.x; a1 += f0.y; a2 += f1.x; a3 += f1.y;
    }
    float di = g_deginv[gwarp];
    a0 *= di; a1 *= di; a2 *= di; a3 *= di;
    float h0 = __bfloat162float(__float2bfloat16_rn(a0));
    float h1 = __bfloat162float(__float2bfloat16_rn(a1));
    float h2 = __bfloat162float(__float2bfloat16_rn(a2));
    float h3 = __bfloat162float(__float2bfloat16_rn(a3));
    __nv_bfloat162 hp0 = __floats2bfloat162_rn(a0, a1);
    __nv_bfloat162 hp1 = __floats2bfloat162_rn(a2, a3);
    __nv_bfloat162 lp0 = __floats2bfloat162_rn(a0 - h0, a1 - h1);
    __nv_bfloat162 lp1 = __floats2bfloat162_rn(a2 - h2, a3 - h3);
    size_t oi = (size_t)gwarp * 32 + lane;
    reinterpret_cast<uint2*>(mh)[oi] = make_uint2(*(uint32_t*)&hp0, *(uint32_t*)&hp1);
    reinterpret_cast<uint2*>(ml)[oi] = make_uint2(*(uint32_t*)&lp0, *(uint32_t*)&lp1);
}

// ================= tensor-core GEMM via mma.sync (preconverted bf16 hi/lo) ========
__device__ __forceinline__ uint32_t smem_u32(const void* p) {
    uint32_t a;
    asm("{ .reg .u64 t; cvta.to.shared.u64 t, %1; cvt.u32.u64 %0, t; }" : "=r"(a) : "l"(p));
    return a;
}
__device__ __forceinline__ void ldsm_x4(uint32_t& r0, uint32_t& r1, uint32_t& r2, uint32_t& r3, uint32_t a) {
    asm volatile("ldmatrix.sync.aligned.m8n8.x4.shared.b16 {%0,%1,%2,%3}, [%4];"
                 : "=r"(r0), "=r"(r1), "=r"(r2), "=r"(r3) : "r"(a));
}
__device__ __forceinline__ void ldsm_x4_t(uint32_t& r0, uint32_t& r1, uint32_t& r2, uint32_t& r3, uint32_t a) {
    asm volatile("ldmatrix.sync.aligned.m8n8.x4.trans.shared.b16 {%0,%1,%2,%3}, [%4];"
                 : "=r"(r0), "=r"(r1), "=r"(r2), "=r"(r3) : "r"(a));
}
__device__ __forceinline__ void mma_bf16(float* c, uint32_t a0, uint32_t a1, uint32_t a2, uint32_t a3,
                                         uint32_t b0, uint32_t b1) {
    asm volatile("mma.sync.aligned.m16n8k16.row.col.f32.bf16.bf16.f32 "
                 "{%0,%1,%2,%3}, {%4,%5,%6,%7}, {%8,%9}, {%0,%1,%2,%3};"
                 : "+f"(c[0]), "+f"(c[1]), "+f"(c[2]), "+f"(c[3])
                 : "r"(a0), "r"(a1), "r"(a2), "r"(a3), "r"(b0), "r"(b1));
}

#define APAD 40
#define BPAD 136

// mode 1: relu, write bf16 hi/lo (outh/outl). mode 0: write fp32 (outf).
__global__ __launch_bounds__(256) void gemm_mma_kernel(
    const __nv_bfloat16* __restrict__ A1h, const __nv_bfloat16* __restrict__ A1l,
    const __nv_bfloat16* __restrict__ A2h, const __nv_bfloat16* __restrict__ A2l,
    const __nv_bfloat16* __restrict__ Wh,  const __nv_bfloat16* __restrict__ Wl,
    const float* __restrict__ bias,
    float* __restrict__ outf, __nv_bfloat16* __restrict__ outh, __nv_bfloat16* __restrict__ outl,
    int mode)
{
    __shared__ __nv_bfloat16 Ah[128][APAD];
    __shared__ __nv_bfloat16 Al[128][APAD];
    __shared__ __nv_bfloat16 Bh[32][BPAD];
    __shared__ __nv_bfloat16 Bl[32][BPAD];

    int tid = threadIdx.x, lane = tid & 31, wid = tid >> 5;
    int warp_m = wid & 3;
    int warp_n = wid >> 2;
    int m0 = blockIdx.x * 128;

    uint32_t ah_b = smem_u32(&Ah[0][0]);
    uint32_t al_b = smem_u32(&Al[0][0]);
    uint32_t bh_b = smem_u32(&Bh[0][0]);
    uint32_t bl_b = smem_u32(&Bl[0][0]);

    float acc[2][8][4];
    #pragma unroll
    for (int i = 0; i < 2; ++i)
        #pragma unroll
        for (int j = 0; j < 8; ++j)
            #pragma unroll
            for (int q = 0; q < 4; ++q) acc[i][j][q] = 0.f;

    int a_lrow = lane & 15;
    int a_lcol = (lane >> 4) << 3;
    int b_lk   = lane & 15;
    int b_ln   = (lane >> 4) << 3;

    for (int ch = 0; ch < 8; ++ch) {
        const __nv_bfloat16* Ahs = (ch < 4) ? A1h : A2h;
        const __nv_bfloat16* Als = (ch < 4) ? A1l : A2l;
        int cb = (ch & 3) * 32;

        __syncthreads();
        // --- A tiles: 2 buffers x 128 rows x 32 cols (uint4 = 8 bf16) ---
        #pragma unroll
        for (int i = 0; i < 4; ++i) {
            int u = tid + i * 256;             // 0..1023
            int buf = u >> 9, r = (u >> 2) & 127, c8 = (u & 3) * 8;
            int gm = m0 + r;
            uint4 v = make_uint4(0u, 0u, 0u, 0u);
            const __nv_bfloat16* s = buf ? Als : Ahs;
            if (gm < NN)
                v = *reinterpret_cast<const uint4*>(s + (size_t)gm * DD + cb + c8);
            __nv_bfloat16* d = buf ? &Al[r][c8] : &Ah[r][c8];
            *reinterpret_cast<uint4*>(d) = v;
        }
        // --- B tiles: 2 buffers x 32 k-rows x 128 cols ---
        #pragma unroll
        for (int i = 0; i < 4; ++i) {
            int u = tid + i * 256;             // 0..1023
            int buf = u >> 9, kr = (u >> 4) & 31, n8 = (u & 15) * 8;
            const __nv_bfloat16* s = buf ? Wl : Wh;
            uint4 v = *reinterpret_cast<const uint4*>(s + (size_t)(ch * 32 + kr) * DD + n8);
            __nv_bfloat16* d = buf ? &Bl[kr][n8] : &Bh[kr][n8];
            *reinterpret_cast<uint4*>(d) = v;
        }
        __syncthreads();

        #pragma unroll
        for (int p = 0; p < 3; ++p) {
            uint32_t ab = (p == 1) ? al_b : ah_b;
            uint32_t bb = (p == 2) ? bl_b : bh_b;
            #pragma unroll
            for (int ks = 0; ks < 2; ++ks) {
                uint32_t a[2][4];
                #pragma unroll
                for (int mt = 0; mt < 2; ++mt) {
                    int row = warp_m * 32 + mt * 16 + a_lrow;
                    int col = ks * 16 + a_lcol;
                    ldsm_x4(a[mt][0], a[mt][1], a[mt][2], a[mt][3],
                            ab + (uint32_t)(row * APAD + col) * 2);
                }
                #pragma unroll
                for (int ng = 0; ng < 4; ++ng) {
                    int kk = ks * 16 + b_lk;
                    int nn = warp_n * 64 + ng * 16 + b_ln;
                    uint32_t b0, b1, b2, b3;
                    ldsm_x4_t(b0, b1, b2, b3, bb + (uint32_t)(kk * BPAD + nn) * 2);
                    #pragma unroll
                    for (int mt = 0; mt < 2; ++mt) {
                        mma_bf16(acc[mt][ng * 2 + 0], a[mt][0], a[mt][1], a[mt][2], a[mt][3], b0, b1);
                        mma_bf16(acc[mt][ng * 2 + 1], a[mt][0], a[mt][1], a[mt][2], a[mt][3], b2, b3);
                    }
                }
            }
        }
    }

    // --- epilogue ---
    int crow = lane >> 2;
    int ccol = (lane & 3) * 2;
    #pragma unroll
    for (int mt = 0; mt < 2; ++mt) {
        #pragma unroll
        for (int nt = 0; nt < 8; ++nt) {
            int col = warp_n * 64 + nt * 8 + ccol;
            float2 bb = __ldg(reinterpret_cast<const float2*>(bias + col));
            #pragma unroll
            for (int h = 0; h < 2; ++h) {
                int row = m0 + warp_m * 32 + mt * 16 + crow + h * 8;
                if (row >= NN) continue;
                float lo = acc[mt][nt][h * 2 + 0] + bb.x;
                float hi = acc[mt][nt][h * 2 + 1] + bb.y;
                if (mode == 1) {
                    lo = fmaxf(lo, 0.f); hi = fmaxf(hi, 0.f);
                    float hlo = __bfloat162float(__float2bfloat16_rn(lo));
                    float hhi = __bfloat162float(__float2bfloat16_rn(hi));
                    __nv_bfloat162 hp = __floats2bfloat162_rn(lo, hi);
                    __nv_bfloat162 lp = __floats2bfloat162_rn(lo - hlo, hi - hhi);
                    *reinterpret_cast<uint32_t*>(outh + (size_t)row * DD + col) = *(uint32_t*)&hp;
                    *reinterpret_cast<uint32_t*>(outl + (size_t)row * DD + col) = *(uint32_t*)&lp;
                } else {
                    *reinterpret_cast<float2*>(outf + (size_t)row * DD + col) = make_float2(lo, hi);
                }
            }
        }
    }
}

// ---------------- launch ----------------
extern "C" void kernel_launch(void* const* d_in, const int* in_sizes, int n_in,
                              void* d_out, int out_size) {
    const float* in_feat  = (const float*)d_in[0];
    const float* W1_self  = (const float*)d_in[1];
    const float* W1_neigh = (const float*)d_in[2];
    const float* b1       = (const float*)d_in[3];
    const float* W2_self  = (const float*)d_in[4];
    const float* W2_neigh = (const float*)d_in[5];
    const float* b2       = (const float*)d_in[6];
    const int*   src      = (const int*)d_in[7];
    const int*   dst      = (const int*)d_in[8];
    float* out = (float*)d_out;

    int* counts_p; cudaGetSymbolAddress((void**)&counts_p, g_counts);
    __nv_bfloat16 *xhi_p, *xlo_p, *mhi_p, *mlo_p, *hhi_p, *hlo_p, *whi_p, *wlo_p;
    cudaGetSymbolAddress((void**)&xhi_p, g_xhi);
    cudaGetSymbolAddress((void**)&xlo_p, g_xlo);
    cudaGetSymbolAddress((void**)&mhi_p, g_mhi);
    cudaGetSymbolAddress((void**)&mlo_p, g_mlo);
    cudaGetSymbolAddress((void**)&hhi_p, g_hhi);
    cudaGetSymbolAddress((void**)&hlo_p, g_hlo);
    cudaGetSymbolAddress((void**)&whi_p, g_whi);
    cudaGetSymbolAddress((void**)&wlo_p, g_wlo);

    // CSR build + conversions
    cudaMemsetAsync(counts_p, 0, NN * sizeof(int));
    hist_kernel<<<(EE + 255) / 256, 256>>>(dst);
    scan_local_kernel<<<NB, 1024>>>();
    finalize_kernel<<<(NN + 255) / 256, 256>>>();
    scatter_kernel<<<(EE + 255) / 256, 256>>>(src, dst);
    convert_x_kernel<<<(NN * DD / 4 + 255) / 256, 256>>>(in_feat);
    convert_w_kernel<<<64, 256>>>(W1_self, W1_neigh, W2_self, W2_neigh);

    int agg_grid  = (NN + 7) / 8;
    int gemm_grid = (NN + 127) / 128;

    // layer 1
    agg_kernel<<<agg_grid, 256>>>(xhi_p, mhi_p, mlo_p);
    gemm_mma_kernel<<<gemm_grid, 256>>>(xhi_p, xlo_p, mhi_p, mlo_p,
                                        whi_p, wlo_p, b1,
                                        nullptr, hhi_p, hlo_p, 1);
    // layer 2
    agg_kernel<<<agg_grid, 256>>>(hhi_p, mhi_p, mlo_p);
    gemm_mma_kernel<<<gemm_grid, 256>>>(hhi_p, hlo_p, mhi_p, mlo_p,
                                        whi_p + 256 * DD, wlo_p + 256 * DD, b2,
                                        out, nullptr, nullptr, 0);
}